// round 1
// baseline (speedup 1.0000x reference)
// TemporalDecoderHierarchical: fused MHA cross-attention, fp32 baseline.
// Pipeline: Q=q@Wq^T, K=kv@Wk^T, V=kv@Wv^T (tiled SGEMM-NT),
//           flash-attention per (b,h) with log-importance bias,
//           out = Y@Wo^T.
// All dims: B=2, Tq=2048, S=4096 (=256*16), D=1024, H=16, d=64.
#include <cuda_runtime.h>
#include <math.h>

#define DM 1024

// Scratch (device globals: allocation-free per harness rules)
__device__ float g_Q[2 * 2048 * 1024];  // 16 MB
__device__ float g_K[2 * 4096 * 1024];  // 32 MB
__device__ float g_V[2 * 4096 * 1024];  // 32 MB
__device__ float g_Y[2 * 2048 * 1024];  // 16 MB

// ---------------------------------------------------------------------------
// SGEMM NT: C[M,N] = A[M,K] @ B[N,K]^T   (both row-major, K contiguous)
// 128x128 tile, BK=16, 256 threads, 8x8 register micro-tile.
// ---------------------------------------------------------------------------
__global__ __launch_bounds__(256) void sgemm_nt(
    const float* __restrict__ A, const float* __restrict__ B,
    float* __restrict__ C, int M, int N, int K)
{
    __shared__ float sA[16][132];  // sA[k][m], padded
    __shared__ float sB[16][132];  // sB[k][n]

    const int tid = threadIdx.x;
    const int tx = tid & 15;        // 0..15  -> n micro
    const int ty = tid >> 4;        // 0..15  -> m micro
    const int m0 = blockIdx.y * 128;
    const int n0 = blockIdx.x * 128;

    float acc[8][8];
#pragma unroll
    for (int i = 0; i < 8; i++)
#pragma unroll
        for (int j = 0; j < 8; j++) acc[i][j] = 0.f;

    for (int k0 = 0; k0 < K; k0 += 16) {
        // Load 128x16 tiles of A and B, transposed into smem (sX[k][row]).
#pragma unroll
        for (int q = 0; q < 2; q++) {
            int f4 = q * 256 + tid;       // 0..511 float4 slots
            int row = f4 >> 2;            // 0..127
            int kq = (f4 & 3) << 2;       // 0,4,8,12
            float4 va = *(const float4*)(A + (size_t)(m0 + row) * K + k0 + kq);
            sA[kq + 0][row] = va.x; sA[kq + 1][row] = va.y;
            sA[kq + 2][row] = va.z; sA[kq + 3][row] = va.w;
            float4 vb = *(const float4*)(B + (size_t)(n0 + row) * K + k0 + kq);
            sB[kq + 0][row] = vb.x; sB[kq + 1][row] = vb.y;
            sB[kq + 2][row] = vb.z; sB[kq + 3][row] = vb.w;
        }
        __syncthreads();

#pragma unroll 8
        for (int k = 0; k < 16; k++) {
            float a[8], b[8];
            *(float4*)&a[0] = *(const float4*)&sA[k][ty * 8];
            *(float4*)&a[4] = *(const float4*)&sA[k][ty * 8 + 4];
            *(float4*)&b[0] = *(const float4*)&sB[k][tx * 8];
            *(float4*)&b[4] = *(const float4*)&sB[k][tx * 8 + 4];
#pragma unroll
            for (int i = 0; i < 8; i++)
#pragma unroll
                for (int j = 0; j < 8; j++)
                    acc[i][j] = fmaf(a[i], b[j], acc[i][j]);
        }
        __syncthreads();
    }

#pragma unroll
    for (int i = 0; i < 8; i++) {
#pragma unroll
        for (int jj = 0; jj < 2; jj++) {
            float4 v = make_float4(acc[i][jj * 4 + 0], acc[i][jj * 4 + 1],
                                   acc[i][jj * 4 + 2], acc[i][jj * 4 + 3]);
            *(float4*)(C + (size_t)(m0 + ty * 8 + i) * N + n0 + tx * 8 + jj * 4) = v;
        }
    }
}

// ---------------------------------------------------------------------------
// Flash attention per (b,h): Q tile 64 rows, KV tiles of 64, d=64.
// 256 threads; thread (ty,tx) owns a 4x4 micro-tile:
//   rows r0=ty*4.. (q rows), cols tx*4.. (kv cols for S / head-dim for O).
// Online softmax with per-row stats replicated across the 16 threads of a row.
// bias[j] = log(clip(imp[b, j%16])) since kv is (t,s) flattened with s fastest.
// ---------------------------------------------------------------------------
__global__ __launch_bounds__(256) void attn_kernel(
    const float* __restrict__ Q, const float* __restrict__ K,
    const float* __restrict__ V, const float* __restrict__ imp,
    float* __restrict__ Y)
{
    extern __shared__ float sm[];
    float* sQt = sm;                 // [64][68] k-major: sQt[k*68 + r]
    float* sKt = sQt + 64 * 68;      // [64][68] k-major: sKt[k*68 + j]
    float* sV  = sKt + 64 * 68;      // [64][68] row-major: sV[j*68 + d]
    float* sPt = sV  + 64 * 68;      // [64][68] j-major:  sPt[j*68 + r]
    float* sImp = sPt + 64 * 68;     // [16]

    const int tid = threadIdx.x;
    const int tx = tid & 15;
    const int ty = tid >> 4;
    const int qt = blockIdx.x;       // 0..31 (q tiles)
    const int bh = blockIdx.y;       // 0..31
    const int b = bh >> 4;
    const int h = bh & 15;

    const size_t qbase  = ((size_t)b * 2048 + qt * 64) * DM + h * 64;
    const size_t kvbase = (size_t)b * 4096 * DM + h * 64;

    if (tid < 16) sImp[tid] = logf(fmaxf(imp[b * 16 + tid], 1e-6f));

    // Load Q tile transposed: sQt[k][r]
#pragma unroll
    for (int q = 0; q < 4; q++) {
        int f4 = q * 256 + tid;        // 0..1023
        int r = f4 >> 4;               // 0..63
        int kq = (f4 & 15) << 2;       // 0..60
        float4 v = *(const float4*)(Q + qbase + (size_t)r * DM + kq);
        sQt[(kq + 0) * 68 + r] = v.x; sQt[(kq + 1) * 68 + r] = v.y;
        sQt[(kq + 2) * 68 + r] = v.z; sQt[(kq + 3) * 68 + r] = v.w;
    }
    __syncthreads();

    float bias[4];
#pragma unroll
    for (int cc = 0; cc < 4; cc++) bias[cc] = sImp[(tx * 4 + cc) & 15];

    float o[4][4];
    float mrun[4], lrun[4];
#pragma unroll
    for (int rr = 0; rr < 4; rr++) {
        mrun[rr] = -1e30f; lrun[rr] = 0.f;
#pragma unroll
        for (int cc = 0; cc < 4; cc++) o[rr][cc] = 0.f;
    }

    for (int t = 0; t < 64; t++) {
        const float* Kt = K + kvbase + (size_t)t * 64 * DM;
        const float* Vt = V + kvbase + (size_t)t * 64 * DM;
        // Load K (transposed) and V (row-major) tiles
#pragma unroll
        for (int q = 0; q < 4; q++) {
            int f4 = q * 256 + tid;
            int j = f4 >> 4;
            int kq = (f4 & 15) << 2;
            float4 vk = *(const float4*)(Kt + (size_t)j * DM + kq);
            sKt[(kq + 0) * 68 + j] = vk.x; sKt[(kq + 1) * 68 + j] = vk.y;
            sKt[(kq + 2) * 68 + j] = vk.z; sKt[(kq + 3) * 68 + j] = vk.w;
            float4 vv = *(const float4*)(Vt + (size_t)j * DM + kq);
            *(float4*)&sV[j * 68 + kq] = vv;
        }
        __syncthreads();

        // S = Q @ K^T (4x4 micro-tile)
        float s[4][4];
#pragma unroll
        for (int rr = 0; rr < 4; rr++)
#pragma unroll
            for (int cc = 0; cc < 4; cc++) s[rr][cc] = 0.f;

#pragma unroll 8
        for (int k = 0; k < 64; k++) {
            float4 qv = *(const float4*)&sQt[k * 68 + ty * 4];
            float4 kv = *(const float4*)&sKt[k * 68 + tx * 4];
            float qa[4] = {qv.x, qv.y, qv.z, qv.w};
            float kb[4] = {kv.x, kv.y, kv.z, kv.w};
#pragma unroll
            for (int rr = 0; rr < 4; rr++)
#pragma unroll
                for (int cc = 0; cc < 4; cc++)
                    s[rr][cc] = fmaf(qa[rr], kb[cc], s[rr][cc]);
        }

        // scale + bias, online softmax update
#pragma unroll
        for (int rr = 0; rr < 4; rr++) {
#pragma unroll
            for (int cc = 0; cc < 4; cc++)
                s[rr][cc] = s[rr][cc] * 0.125f + bias[cc];
            float mx = fmaxf(fmaxf(s[rr][0], s[rr][1]), fmaxf(s[rr][2], s[rr][3]));
            mx = fmaxf(mx, __shfl_xor_sync(0xffffffffu, mx, 1));
            mx = fmaxf(mx, __shfl_xor_sync(0xffffffffu, mx, 2));
            mx = fmaxf(mx, __shfl_xor_sync(0xffffffffu, mx, 4));
            mx = fmaxf(mx, __shfl_xor_sync(0xffffffffu, mx, 8));
            float mnew = fmaxf(mrun[rr], mx);
            float corr = __expf(mrun[rr] - mnew);
            float rs = 0.f;
#pragma unroll
            for (int cc = 0; cc < 4; cc++) {
                float p = __expf(s[rr][cc] - mnew);
                s[rr][cc] = p;
                rs += p;
            }
            rs += __shfl_xor_sync(0xffffffffu, rs, 1);
            rs += __shfl_xor_sync(0xffffffffu, rs, 2);
            rs += __shfl_xor_sync(0xffffffffu, rs, 4);
            rs += __shfl_xor_sync(0xffffffffu, rs, 8);
            lrun[rr] = lrun[rr] * corr + rs;
            mrun[rr] = mnew;
#pragma unroll
            for (int cc = 0; cc < 4; cc++) o[rr][cc] *= corr;
        }

        // Write P transposed: sPt[j][r]
#pragma unroll
        for (int cc = 0; cc < 4; cc++) {
            float4 pv = make_float4(s[0][cc], s[1][cc], s[2][cc], s[3][cc]);
            *(float4*)&sPt[(tx * 4 + cc) * 68 + ty * 4] = pv;
        }
        __syncthreads();

        // O += P @ V
#pragma unroll 8
        for (int j = 0; j < 64; j++) {
            float4 pv = *(const float4*)&sPt[j * 68 + ty * 4];
            float4 vv = *(const float4*)&sV[j * 68 + tx * 4];
            float pa[4] = {pv.x, pv.y, pv.z, pv.w};
            float vb[4] = {vv.x, vv.y, vv.z, vv.w};
#pragma unroll
            for (int rr = 0; rr < 4; rr++)
#pragma unroll
                for (int cc = 0; cc < 4; cc++)
                    o[rr][cc] = fmaf(pa[rr], vb[cc], o[rr][cc]);
        }
        __syncthreads();
    }

    // Epilogue: normalize, write merged-head layout Y[b, q, h*64 + d]
#pragma unroll
    for (int rr = 0; rr < 4; rr++) {
        float inv = 1.f / lrun[rr];
        float4 outv = make_float4(o[rr][0] * inv, o[rr][1] * inv,
                                  o[rr][2] * inv, o[rr][3] * inv);
        *(float4*)(Y + qbase + (size_t)(ty * 4 + rr) * DM + tx * 4) = outv;
    }
}

// ---------------------------------------------------------------------------
extern "C" void kernel_launch(void* const* d_in, const int* in_sizes, int n_in,
                              void* d_out, int out_size)
{
    const float* q   = (const float*)d_in[0];  // [2,2048,1024]
    const float* kv  = (const float*)d_in[1];  // [2,256,16,1024] == [2,4096,1024]
    const float* imp = (const float*)d_in[2];  // [2,16]
    const float* Wq  = (const float*)d_in[3];
    const float* Wk  = (const float*)d_in[4];
    const float* Wv  = (const float*)d_in[5];
    const float* Wo  = (const float*)d_in[6];
    float* out = (float*)d_out;

    float *pQ, *pK, *pV, *pY;
    cudaGetSymbolAddress((void**)&pQ, g_Q);
    cudaGetSymbolAddress((void**)&pK, g_K);
    cudaGetSymbolAddress((void**)&pV, g_V);
    cudaGetSymbolAddress((void**)&pY, g_Y);

    const int ATT_SMEM = (4 * 64 * 68 + 16) * 4;  // 69696 bytes
    cudaFuncSetAttribute(attn_kernel, cudaFuncAttributeMaxDynamicSharedMemorySize,
                         ATT_SMEM);

    // Projections
    sgemm_nt<<<dim3(8, 32), 256>>>(q,  Wq, pQ, 4096, 1024, 1024);
    sgemm_nt<<<dim3(8, 64), 256>>>(kv, Wk, pK, 8192, 1024, 1024);
    sgemm_nt<<<dim3(8, 64), 256>>>(kv, Wv, pV, 8192, 1024, 1024);
    // Attention: grid (qtiles=32, b*h=32)
    attn_kernel<<<dim3(32, 32), 256, ATT_SMEM>>>(pQ, pK, pV, imp, pY);
    // Output projection
    sgemm_nt<<<dim3(8, 32), 256>>>(pY, Wo, out, 4096, 1024, 1024);
}

// round 2
// speedup vs baseline: 1.5294x; 1.5294x over previous
// TemporalDecoderHierarchical: MHA cross-attention, tf32 tensor-core version.
// All GEMMs (Q/K/V/O projections, QK^T, PV) via mma.sync.m16n8k8 tf32 with
// cvt.rna.tf32 rounding and fp32 accumulation.
// Dims: B=2, Tq=2048, S=4096, D=1024, H=16, d=64.
#include <cuda_runtime.h>
#include <math.h>

#define DM 1024

__device__ float g_Q[2 * 2048 * 1024];
__device__ float g_K[2 * 4096 * 1024];
__device__ float g_V[2 * 4096 * 1024];
__device__ float g_Y[2 * 2048 * 1024];

__device__ __forceinline__ unsigned f2tf(float f) {
    unsigned u;
    asm("cvt.rna.tf32.f32 %0, %1;" : "=r"(u) : "f"(f));
    return u;
}

__device__ __forceinline__ void mma_tf32(float c[4], const unsigned a[4],
                                         const unsigned b[2]) {
    asm("mma.sync.aligned.m16n8k8.row.col.f32.tf32.tf32.f32 "
        "{%0,%1,%2,%3},{%4,%5,%6,%7},{%8,%9},{%0,%1,%2,%3};"
        : "+f"(c[0]), "+f"(c[1]), "+f"(c[2]), "+f"(c[3])
        : "r"(a[0]), "r"(a[1]), "r"(a[2]), "r"(a[3]), "r"(b[0]), "r"(b[1]));
}

// ---------------------------------------------------------------------------
// GEMM NT: C[M,N] = A[M,K] @ B[N,K]^T, tf32 tensor cores.
// 128x128x16 block tile, 256 threads = 8 warps (2m x 4n), warp tile 64x32.
// ---------------------------------------------------------------------------
__global__ __launch_bounds__(256, 2) void gemm_tf32_nt(
    const float* __restrict__ A, const float* __restrict__ B,
    float* __restrict__ C, int M, int N, int K)
{
    __shared__ unsigned sA[16][136];  // [k][m]
    __shared__ unsigned sB[16][136];  // [k][n]

    const int tid = threadIdx.x;
    const int lane = tid & 31, warp = tid >> 5;
    const int g = lane >> 2, tig = lane & 3;
    const int wm = warp & 1, wn = warp >> 1;
    const int m0 = blockIdx.y * 128, n0 = blockIdx.x * 128;

    float c[4][4][4];
#pragma unroll
    for (int mt = 0; mt < 4; mt++)
#pragma unroll
        for (int nt = 0; nt < 4; nt++)
#pragma unroll
            for (int i = 0; i < 4; i++) c[mt][nt][i] = 0.f;

    for (int k0 = 0; k0 < K; k0 += 16) {
#pragma unroll
        for (int q = 0; q < 2; q++) {
            int f4 = q * 256 + tid;
            int row = f4 >> 2;
            int kq = (f4 & 3) << 2;
            float4 va = *(const float4*)(A + (size_t)(m0 + row) * K + k0 + kq);
            sA[kq + 0][row] = f2tf(va.x); sA[kq + 1][row] = f2tf(va.y);
            sA[kq + 2][row] = f2tf(va.z); sA[kq + 3][row] = f2tf(va.w);
            float4 vb = *(const float4*)(B + (size_t)(n0 + row) * K + k0 + kq);
            sB[kq + 0][row] = f2tf(vb.x); sB[kq + 1][row] = f2tf(vb.y);
            sB[kq + 2][row] = f2tf(vb.z); sB[kq + 3][row] = f2tf(vb.w);
        }
        __syncthreads();

#pragma unroll
        for (int ks = 0; ks < 2; ks++) {
            const int kk = ks * 8;
            unsigned a[4][4], b[4][2];
#pragma unroll
            for (int mt = 0; mt < 4; mt++) {
                int mr = wm * 64 + mt * 16;
                a[mt][0] = sA[kk + tig][mr + g];
                a[mt][1] = sA[kk + tig][mr + g + 8];
                a[mt][2] = sA[kk + tig + 4][mr + g];
                a[mt][3] = sA[kk + tig + 4][mr + g + 8];
            }
#pragma unroll
            for (int nt = 0; nt < 4; nt++) {
                int nb = wn * 32 + nt * 8;
                b[nt][0] = sB[kk + tig][nb + g];
                b[nt][1] = sB[kk + tig + 4][nb + g];
            }
#pragma unroll
            for (int mt = 0; mt < 4; mt++)
#pragma unroll
                for (int nt = 0; nt < 4; nt++)
                    mma_tf32(c[mt][nt], a[mt], b[nt]);
        }
        __syncthreads();
    }

#pragma unroll
    for (int mt = 0; mt < 4; mt++) {
#pragma unroll
        for (int nt = 0; nt < 4; nt++) {
            int row = m0 + wm * 64 + mt * 16 + g;
            int col = n0 + wn * 32 + nt * 8 + 2 * tig;
            *(float2*)(C + (size_t)row * N + col) =
                make_float2(c[mt][nt][0], c[mt][nt][1]);
            *(float2*)(C + (size_t)(row + 8) * N + col) =
                make_float2(c[mt][nt][2], c[mt][nt][3]);
        }
    }
}

// ---------------------------------------------------------------------------
// Flash attention, tf32 tensor cores. Per (b,h): q-tile 64 rows (4 warps x
// 16 rows), kv tiles of 64, d=64. Online softmax in fp32 on C fragments.
// ---------------------------------------------------------------------------
#define SQ 73  // stride (uints) for k-major transposed tiles (2-way max conflicts)
#define SVS 72 // stride for row-major V tile (conflict-free frag loads)

__global__ __launch_bounds__(128) void attn_tf32(
    const float* __restrict__ Qg, const float* __restrict__ Kg,
    const float* __restrict__ Vg, const float* __restrict__ imp,
    float* __restrict__ Y)
{
    extern __shared__ unsigned smu[];
    unsigned* sQt = smu;               // [64][SQ]  k(d)-major: Q^T
    unsigned* sKt = sQt + 64 * SQ;     // [64][SQ]  k(d)-major: K^T
    unsigned* sPt = sKt + 64 * SQ;     // [64][SQ]  k(j)-major: P^T (warp-private cols)
    unsigned* sV  = sPt + 64 * SQ;     // [64][SVS] row-major: V
    float* sImp = (float*)(sV + 64 * SVS);  // [16]

    const int tid = threadIdx.x;
    const int lane = tid & 31, w = tid >> 5;
    const int g = lane >> 2, tig = lane & 3;
    const int qt = blockIdx.x;
    const int bh = blockIdx.y;
    const int b = bh >> 4, h = bh & 15;
    const int m0 = w * 16;

    const size_t qbase  = ((size_t)b * 2048 + qt * 64) * DM + h * 64;
    const size_t kvbase = (size_t)b * 4096 * DM + h * 64;

    if (tid < 16) sImp[tid] = logf(fmaxf(imp[b * 16 + tid], 1e-6f));

    // Load Q tile (64x64) transposed + tf32-rounded
#pragma unroll
    for (int it = 0; it < 8; it++) {
        int f4 = it * 128 + tid;
        int r = f4 >> 4;
        int kq = (f4 & 15) << 2;
        float4 v = *(const float4*)(Qg + qbase + (size_t)r * DM + kq);
        sQt[(kq + 0) * SQ + r] = f2tf(v.x);
        sQt[(kq + 1) * SQ + r] = f2tf(v.y);
        sQt[(kq + 2) * SQ + r] = f2tf(v.z);
        sQt[(kq + 3) * SQ + r] = f2tf(v.w);
    }
    __syncthreads();

    float bias0[8], bias1[8];
#pragma unroll
    for (int nt = 0; nt < 8; nt++) {
        int c0 = nt * 8 + 2 * tig;
        bias0[nt] = sImp[c0 & 15];
        bias1[nt] = sImp[(c0 + 1) & 15];
    }

    float o[8][4];
#pragma unroll
    for (int nt = 0; nt < 8; nt++)
#pragma unroll
        for (int i = 0; i < 4; i++) o[nt][i] = 0.f;
    float mrow[2] = {-1e30f, -1e30f};
    float lrow[2] = {0.f, 0.f};

    for (int t = 0; t < 64; t++) {
        const float* Kt = Kg + kvbase + (size_t)t * 64 * DM;
        const float* Vt = Vg + kvbase + (size_t)t * 64 * DM;
#pragma unroll
        for (int it = 0; it < 8; it++) {
            int f4 = it * 128 + tid;
            int j = f4 >> 4;
            int kq = (f4 & 15) << 2;
            float4 vk = *(const float4*)(Kt + (size_t)j * DM + kq);
            sKt[(kq + 0) * SQ + j] = f2tf(vk.x);
            sKt[(kq + 1) * SQ + j] = f2tf(vk.y);
            sKt[(kq + 2) * SQ + j] = f2tf(vk.z);
            sKt[(kq + 3) * SQ + j] = f2tf(vk.w);
            float4 vv = *(const float4*)(Vt + (size_t)j * DM + kq);
            uint4 uv;
            uv.x = f2tf(vv.x); uv.y = f2tf(vv.y);
            uv.z = f2tf(vv.z); uv.w = f2tf(vv.w);
            *(uint4*)&sV[j * SVS + kq] = uv;
        }
        __syncthreads();

        // S = Q @ K^T  (each warp: 16 q-rows x 64 kv-cols)
        float s[8][4];
#pragma unroll
        for (int nt = 0; nt < 8; nt++)
#pragma unroll
            for (int i = 0; i < 4; i++) s[nt][i] = 0.f;

#pragma unroll
        for (int kk2 = 0; kk2 < 8; kk2++) {
            const int kk = kk2 * 8;
            unsigned a[4];
            a[0] = sQt[(kk + tig) * SQ + m0 + g];
            a[1] = sQt[(kk + tig) * SQ + m0 + g + 8];
            a[2] = sQt[(kk + tig + 4) * SQ + m0 + g];
            a[3] = sQt[(kk + tig + 4) * SQ + m0 + g + 8];
#pragma unroll
            for (int nt = 0; nt < 8; nt++) {
                unsigned bb[2];
                bb[0] = sKt[(kk + tig) * SQ + nt * 8 + g];
                bb[1] = sKt[(kk + tig + 4) * SQ + nt * 8 + g];
                mma_tf32(s[nt], a, bb);
            }
        }

        // Online softmax (rows g and g+8 of this warp's 16-row stripe)
#pragma unroll
        for (int half = 0; half < 2; half++) {
            float mx = -1e30f;
#pragma unroll
            for (int nt = 0; nt < 8; nt++) {
                float v0 = s[nt][half * 2] * 0.125f + bias0[nt];
                float v1 = s[nt][half * 2 + 1] * 0.125f + bias1[nt];
                s[nt][half * 2] = v0;
                s[nt][half * 2 + 1] = v1;
                mx = fmaxf(mx, fmaxf(v0, v1));
            }
            mx = fmaxf(mx, __shfl_xor_sync(0xffffffffu, mx, 1));
            mx = fmaxf(mx, __shfl_xor_sync(0xffffffffu, mx, 2));
            float mnew = fmaxf(mrow[half], mx);
            float corr = __expf(mrow[half] - mnew);
            float rs = 0.f;
#pragma unroll
            for (int nt = 0; nt < 8; nt++) {
                float p0 = __expf(s[nt][half * 2] - mnew);
                float p1 = __expf(s[nt][half * 2 + 1] - mnew);
                s[nt][half * 2] = p0;
                s[nt][half * 2 + 1] = p1;
                rs += p0 + p1;
            }
            rs += __shfl_xor_sync(0xffffffffu, rs, 1);
            rs += __shfl_xor_sync(0xffffffffu, rs, 2);
            lrow[half] = lrow[half] * corr + rs;
            mrow[half] = mnew;
#pragma unroll
            for (int nt = 0; nt < 8; nt++) {
                o[nt][half * 2] *= corr;
                o[nt][half * 2 + 1] *= corr;
            }
        }

        // P^T into smem (warp-private columns m0..m0+15)
#pragma unroll
        for (int nt = 0; nt < 8; nt++) {
            int j0 = nt * 8 + 2 * tig;
            sPt[j0 * SQ + m0 + g]           = f2tf(s[nt][0]);
            sPt[(j0 + 1) * SQ + m0 + g]     = f2tf(s[nt][1]);
            sPt[j0 * SQ + m0 + g + 8]       = f2tf(s[nt][2]);
            sPt[(j0 + 1) * SQ + m0 + g + 8] = f2tf(s[nt][3]);
        }
        __syncwarp();

        // O += P @ V
#pragma unroll
        for (int kk2 = 0; kk2 < 8; kk2++) {
            const int kk = kk2 * 8;
            unsigned a[4];
            a[0] = sPt[(kk + tig) * SQ + m0 + g];
            a[1] = sPt[(kk + tig) * SQ + m0 + g + 8];
            a[2] = sPt[(kk + tig + 4) * SQ + m0 + g];
            a[3] = sPt[(kk + tig + 4) * SQ + m0 + g + 8];
#pragma unroll
            for (int nt = 0; nt < 8; nt++) {
                unsigned bb[2];
                bb[0] = sV[(kk + tig) * SVS + nt * 8 + g];
                bb[1] = sV[(kk + tig + 4) * SVS + nt * 8 + g];
                mma_tf32(o[nt], a, bb);
            }
        }
        __syncthreads();
    }

    // Epilogue: normalize, write merged-head layout
    float inv0 = 1.f / lrow[0];
    float inv1 = 1.f / lrow[1];
#pragma unroll
    for (int nt = 0; nt < 8; nt++) {
        int col = nt * 8 + 2 * tig;
        *(float2*)(Y + qbase + (size_t)(m0 + g) * DM + col) =
            make_float2(o[nt][0] * inv0, o[nt][1] * inv0);
        *(float2*)(Y + qbase + (size_t)(m0 + g + 8) * DM + col) =
            make_float2(o[nt][2] * inv1, o[nt][3] * inv1);
    }
}

// ---------------------------------------------------------------------------
extern "C" void kernel_launch(void* const* d_in, const int* in_sizes, int n_in,
                              void* d_out, int out_size)
{
    const float* q   = (const float*)d_in[0];
    const float* kv  = (const float*)d_in[1];
    const float* imp = (const float*)d_in[2];
    const float* Wq  = (const float*)d_in[3];
    const float* Wk  = (const float*)d_in[4];
    const float* Wv  = (const float*)d_in[5];
    const float* Wo  = (const float*)d_in[6];
    float* out = (float*)d_out;

    float *pQ, *pK, *pV, *pY;
    cudaGetSymbolAddress((void**)&pQ, g_Q);
    cudaGetSymbolAddress((void**)&pK, g_K);
    cudaGetSymbolAddress((void**)&pV, g_V);
    cudaGetSymbolAddress((void**)&pY, g_Y);

    const int ATT_SMEM = (64 * SQ * 3 + 64 * SVS) * 4 + 64;
    cudaFuncSetAttribute(attn_tf32, cudaFuncAttributeMaxDynamicSharedMemorySize,
                         ATT_SMEM);

    gemm_tf32_nt<<<dim3(8, 32), 256>>>(q,  Wq, pQ, 4096, 1024, 1024);
    gemm_tf32_nt<<<dim3(8, 64), 256>>>(kv, Wk, pK, 8192, 1024, 1024);
    gemm_tf32_nt<<<dim3(8, 64), 256>>>(kv, Wv, pV, 8192, 1024, 1024);
    attn_tf32<<<dim3(32, 32), 128, ATT_SMEM>>>(pQ, pK, pV, imp, pY);
    gemm_tf32_nt<<<dim3(8, 32), 256>>>(pY, Wo, out, 4096, 1024, 1024);
}